// round 1
// baseline (speedup 1.0000x reference)
#include <cuda_runtime.h>
#include <math_constants.h>
#include <cstdint>
#include <cstddef>

// Problem constants
#define NDIM 8192
#define CDIM 16
#define K_EDGES 131072
#define MAXDEG 64
#define CAP 512

static constexpr size_t NN = (size_t)NDIM * (size_t)NDIM;
static constexpr size_t NSLOTS = (size_t)NDIM * (size_t)CAP;

// ---------------- device scratch (static: no allocation allowed) ----------------
__device__ float         g_P[NN];             // rebalanced key, upper triangle only (256MB)
__device__ int           g_labels[NDIM];
__device__ double        g_sameMass, g_diffMass;
__device__ float         g_wsame, g_wdiff;
__device__ int           g_skip;
__device__ unsigned int  g_hist1[4096];
__device__ unsigned int  g_hist2[4096];
__device__ unsigned int  g_hist3[256];
__device__ unsigned int  g_b1, g_b12;         // selected radix prefixes
__device__ unsigned int  g_thrBits;           // exact 32-bit threshold bit pattern
__device__ unsigned int  g_cntGt1, g_cntGt2;  // cumulative strictly-greater counts
__device__ unsigned int  g_needEq;            // how many ==thr entries to take (lowest flat idx)
__device__ int           g_nbr[NSLOTS];       // neighbor index per slot
__device__ float         g_pf[NSLOTS];        // probs[i][j] for slot (i->j)
__device__ float         g_pr[NSLOTS];        // probs[j][i] for slot (i->j)
__device__ unsigned char g_act[NSLOTS];       // edge-slot active flag
__device__ int           g_deg[NDIM];         // emission counter
__device__ float         g_thr[NDIM];         // per-row 64th-largest neighbor prob
__device__ unsigned char g_keepall[NDIM];     // deg <= 64
__device__ unsigned int  g_eqIdx[K_EDGES];
__device__ unsigned int  g_eqCnt;

// ---------------- kernels ----------------

__global__ void clearK() {
    size_t idx = blockIdx.x * (size_t)blockDim.x + threadIdx.x;
    size_t stride = (size_t)gridDim.x * blockDim.x;
    for (size_t k = idx; k < NSLOTS; k += stride) g_act[k] = 0;
    if (idx < 4096) { g_hist1[idx] = 0; g_hist2[idx] = 0; }
    if (idx < 256)  { g_hist3[idx] = 0; }
    if (idx < NDIM) { g_deg[idx] = 0; }
    if (idx == 0)   { g_sameMass = 0.0; g_diffMass = 0.0; g_eqCnt = 0; }
}

__global__ void argmaxK(const float* __restrict__ lp) {
    int i = blockIdx.x * blockDim.x + threadIdx.x;
    if (i >= NDIM) return;
    float best = lp[(size_t)i * CDIM];
    int bi = 0;
#pragma unroll
    for (int c = 1; c < CDIM; c++) {
        float v = lp[(size_t)i * CDIM + c];
        if (v > best) { best = v; bi = c; }  // strict >: first max wins (matches argmax)
    }
    g_labels[i] = bi;
}

__global__ void massK(const float* __restrict__ adj) {
    double s = 0.0, d = 0.0;
    size_t stride = (size_t)gridDim.x * blockDim.x;
    for (size_t idx = blockIdx.x * (size_t)blockDim.x + threadIdx.x; idx < NN; idx += stride) {
        float a = adj[idx];
        unsigned i = (unsigned)(idx >> 13), j = (unsigned)(idx & 8191u);
        // same = (labels equal) & off-diagonal; diff = everything else (incl. diagonal)
        if (i != j && g_labels[i] == g_labels[j]) s += (double)a; else d += (double)a;
    }
    __shared__ double ss[256], sd[256];
    int t = threadIdx.x;
    ss[t] = s; sd[t] = d;
    __syncthreads();
    for (int off = 128; off > 0; off >>= 1) {
        if (t < off) { ss[t] += ss[t + off]; sd[t] += sd[t + off]; }
        __syncthreads();
    }
    if (t == 0) { atomicAdd(&g_sameMass, ss[0]); atomicAdd(&g_diffMass, sd[0]); }
}

__global__ void decideK() {
    double sm = g_sameMass, dm = g_diffMass;
    double total = sm + dm;
    float cur = (float)(sm / total);
    float ws = fminf(fmaxf(0.7f / (cur + 1e-6f), (float)(1.0 / 3.0)), 3.0f);
    float wd = fminf(fmaxf((float)(1.0 - 0.7) / (1.0f - cur + 1e-6f), (float)(1.0 / 3.0)), 3.0f);
    g_wsame = ws; g_wdiff = wd;
    g_skip = (sm <= 1e-6 || dm <= 1e-6 || fabsf(cur - 0.7f) <= 0.05f) ? 1 : 0;
}

// Compute P upper triangle + level-1 radix histogram (bits >> 20).
__global__ void pmatK(const float* __restrict__ adj) {
    int bi = blockIdx.y, bj = blockIdx.x;
    if (bj < bi) return;  // upper 64x64 blocks only
    __shared__ float sAt[64][65];
    __shared__ unsigned int sh[4096];
    __shared__ int sli[64], slj[64];
    int t = threadIdx.x;  // 256 threads
    for (int k = t; k < 4096; k += 256) sh[k] = 0;
    if (t < 64) { sli[t] = g_labels[bi * 64 + t]; slj[t] = g_labels[bj * 64 + t]; }
    // transposed tile: sAt[r2][c2] = adj[bj*64+r2][bi*64+c2]
    for (int e = t; e < 64 * 64; e += 256) {
        int r2 = e >> 6, c2 = e & 63;
        sAt[r2][c2] = adj[(size_t)(bj * 64 + r2) * NDIM + (size_t)(bi * 64 + c2)];
    }
    __syncthreads();
    int skip = g_skip;
    float ws = g_wsame, wd = g_wdiff;
    for (int e = t; e < 64 * 64; e += 256) {
        int r = e >> 6, c = e & 63;
        int i = bi * 64 + r, j = bj * 64 + c;
        if (j > i) {
            float a1 = adj[(size_t)i * NDIM + j];
            float p;
            if (skip) {
                p = a1;  // probs = original adj_probs
            } else {
                float a2 = sAt[c][r];  // adj[j][i]
                float w = (sli[r] == slj[c]) ? ws : wd;
                // match XLA rounding: separate muls, one add, exact *0.5
                p = 0.5f * __fadd_rn(__fmul_rn(a1, w), __fmul_rn(a2, w));
            }
            g_P[(size_t)i * NDIM + j] = p;
            atomicAdd(&sh[__float_as_uint(p) >> 20], 1u);
        }
    }
    __syncthreads();
    for (int k = t; k < 4096; k += 256)
        if (sh[k]) atomicAdd(&g_hist1[k], sh[k]);
}

__global__ void scan1K() {
    unsigned cum = 0;
    for (int k = 4095; k >= 0; k--) {
        unsigned h = g_hist1[k];
        if (cum + h >= (unsigned)K_EDGES) { g_b1 = (unsigned)k; g_cntGt1 = cum; return; }
        cum += h;
    }
    g_b1 = 0; g_cntGt1 = cum;
}

__global__ void hist2K() {
    __shared__ unsigned int sh[4096];
    int t = threadIdx.x;
    for (int k = t; k < 4096; k += 256) sh[k] = 0;
    __syncthreads();
    int i = blockIdx.x;
    unsigned b1 = g_b1;
    const float* row = g_P + (size_t)i * NDIM;
    for (int j = i + 1 + t; j < NDIM; j += 256) {
        unsigned bits = __float_as_uint(row[j]);
        if ((bits >> 20) == b1) atomicAdd(&sh[(bits >> 8) & 0xFFFu], 1u);
    }
    __syncthreads();
    for (int k = t; k < 4096; k += 256)
        if (sh[k]) atomicAdd(&g_hist2[k], sh[k]);
}

__global__ void scan2K() {
    unsigned cum = g_cntGt1;
    for (int k = 4095; k >= 0; k--) {
        unsigned h = g_hist2[k];
        if (cum + h >= (unsigned)K_EDGES) {
            g_b12 = (g_b1 << 12) | (unsigned)k; g_cntGt2 = cum; return;
        }
        cum += h;
    }
    g_b12 = (g_b1 << 12); g_cntGt2 = cum;
}

__global__ void hist3K() {
    __shared__ unsigned int sh[256];
    int t = threadIdx.x;
    if (t < 256) sh[t] = 0;
    __syncthreads();
    int i = blockIdx.x;
    unsigned b12 = g_b12;
    const float* row = g_P + (size_t)i * NDIM;
    for (int j = i + 1 + t; j < NDIM; j += 256) {
        unsigned bits = __float_as_uint(row[j]);
        if ((bits >> 8) == b12) atomicAdd(&sh[bits & 0xFFu], 1u);
    }
    __syncthreads();
    if (t < 256 && sh[t]) atomicAdd(&g_hist3[t], sh[t]);
}

__global__ void scan3K() {
    unsigned cum = g_cntGt2;
    for (int k = 255; k >= 0; k--) {
        unsigned h = g_hist3[k];
        if (cum + h >= (unsigned)K_EDGES) {
            g_thrBits = (g_b12 << 8) | (unsigned)k;
            g_needEq = (unsigned)K_EDGES - cum;
            return;
        }
        cum += h;
    }
    g_thrBits = (g_b12 << 8);
    g_needEq = 0;
}

__device__ __forceinline__ void emitEdge(int i, int j, float p, const float* __restrict__ adj, int skip) {
    float pf_i, pr_i, pf_j, pr_j;
    if (skip) {
        float aij = adj[(size_t)i * NDIM + j];
        float aji = adj[(size_t)j * NDIM + i];
        pf_i = aij; pr_i = aji; pf_j = aji; pr_j = aij;
    } else {
        pf_i = pr_i = pf_j = pr_j = p;  // symmetric
    }
    int di = atomicAdd(&g_deg[i], 1);
    if (di < CAP) {
        size_t s = (size_t)i * CAP + di;
        g_nbr[s] = j; g_pf[s] = pf_i; g_pr[s] = pr_i; g_act[s] = 1;
    }
    int dj = atomicAdd(&g_deg[j], 1);
    if (dj < CAP) {
        size_t s = (size_t)j * CAP + dj;
        g_nbr[s] = i; g_pf[s] = pf_j; g_pr[s] = pr_j; g_act[s] = 1;
    }
}

__global__ void selectK(const float* __restrict__ adj) {
    int i = blockIdx.x;
    int t = threadIdx.x;
    unsigned thr = g_thrBits;
    int skip = g_skip;
    const float* row = g_P + (size_t)i * NDIM;
    for (int j = i + 1 + t; j < NDIM; j += 256) {
        float p = row[j];
        unsigned bits = __float_as_uint(p);
        if (bits > thr) {
            emitEdge(i, j, p, adj, skip);
        } else if (bits == thr) {
            unsigned pos = atomicAdd(&g_eqCnt, 1u);
            if (pos < (unsigned)K_EDGES)
                g_eqIdx[pos] = (unsigned)i * (unsigned)NDIM + (unsigned)j;
        }
    }
}

// Take the g_needEq lowest flat indices among entries equal to the threshold
// (matches lax.top_k tie-break: lower index wins).
__global__ void resolveK(const float* __restrict__ adj) {
    unsigned M = min(g_eqCnt, (unsigned)K_EDGES);
    unsigned need = g_needEq;
    int skip = g_skip;
    if (need == 0) return;
    unsigned stride = gridDim.x * blockDim.x;
    for (unsigned t = blockIdx.x * blockDim.x + threadIdx.x; t < M; t += stride) {
        unsigned idx = g_eqIdx[t];
        unsigned rank = 0;
        for (unsigned s = 0; s < M; s++) rank += (g_eqIdx[s] < idx) ? 1u : 0u;
        if (rank < need) {
            int i = (int)(idx >> 13), j = (int)(idx & 8191u);
            emitEdge(i, j, g_P[(size_t)i * NDIM + j], adj, skip);
        }
    }
}

// Per-row degree + 64th-largest active neighbor prob (top_k semantics).
__global__ void threshK() {
    int i = blockIdx.x;
    int t = threadIdx.x;  // 128 threads
    __shared__ float vals[CAP];
    __shared__ int cnt;
    __shared__ unsigned red[128];
    if (t == 0) cnt = 0;
    __syncthreads();
    size_t base = (size_t)i * CAP;
    for (int s = t; s < CAP; s += 128) {
        if (g_act[base + s]) {
            int pos = atomicAdd(&cnt, 1);
            vals[pos] = g_pf[base + s];
        }
    }
    __syncthreads();
    int deg = cnt;
    if (deg <= MAXDEG) {
        if (t == 0) { g_keepall[i] = 1; g_thr[i] = -CUDART_INF_F; }
        return;
    }
    if (t == 0) g_keepall[i] = 0;
    // 64th largest value: largest bit pattern T with count(bits >= T) >= 64.
    // All probs are >= 0, so uint order == float order.
    unsigned T = 0;
    for (int b = 31; b >= 0; b--) {
        unsigned cand = T | (1u << b);
        unsigned c = 0;
        for (int s = t; s < deg; s += 128)
            c += (__float_as_uint(vals[s]) >= cand) ? 1u : 0u;
        red[t] = c;
        __syncthreads();
        for (int off = 64; off > 0; off >>= 1) {
            if (t < off) red[t] += red[t + off];
            __syncthreads();
        }
        unsigned tot = red[0];
        __syncthreads();
        if (tot >= (unsigned)MAXDEG) T = cand;
    }
    if (t == 0) g_thr[i] = __uint_as_float(T);
}

__global__ void filterK() {
    size_t idx = blockIdx.x * (size_t)blockDim.x + threadIdx.x;
    if (idx >= NSLOTS) return;
    if (!g_act[idx]) return;
    int i = (int)(idx / CAP);
    int j = g_nbr[idx];
    float pf = g_pf[idx], pr = g_pr[idx];
    bool ki = g_keepall[i] || (pf >= g_thr[i]);
    bool kj = g_keepall[j] || (pr >= g_thr[j]);
    if (!(ki && kj)) g_act[idx] = 0;
}

__global__ void scatterK(float* __restrict__ out) {
    size_t idx = blockIdx.x * (size_t)blockDim.x + threadIdx.x;
    if (idx >= NSLOTS) return;
    if (!g_act[idx]) return;
    int i = (int)(idx / CAP);
    int j = g_nbr[idx];
    out[(size_t)i * NDIM + j] = 1.0f;  // each edge lives in both rows' slots
}

// ---------------- launch ----------------
extern "C" void kernel_launch(void* const* d_in, const int* in_sizes, int n_in,
                              void* d_out, int out_size) {
    const float* adj = (const float*)d_in[0];   // adj_probs [N, N]
    const float* lp  = (const float*)d_in[1];   // label_probs [N, C]
    float* out = (float*)d_out;

    clearK<<<4096, 1024>>>();
    argmaxK<<<NDIM / 256, 256>>>(lp);
    massK<<<2048, 256>>>(adj);
    decideK<<<1, 1>>>();
    {
        dim3 grid(128, 128);
        pmatK<<<grid, 256>>>(adj);
    }
    scan1K<<<1, 1>>>();
    hist2K<<<NDIM, 256>>>();
    scan2K<<<1, 1>>>();
    hist3K<<<NDIM, 256>>>();
    scan3K<<<1, 1>>>();
    selectK<<<NDIM, 256>>>(adj);
    resolveK<<<64, 256>>>(adj);

    for (int it = 0; it < 10; it++) {
        threshK<<<NDIM, 128>>>();
        filterK<<<(int)(NSLOTS / 256), 256>>>();
    }

    cudaMemsetAsync(d_out, 0, NN * sizeof(float), 0);
    scatterK<<<(int)(NSLOTS / 256), 256>>>(out);
}

// round 2
// speedup vs baseline: 2.3598x; 2.3598x over previous
#include <cuda_runtime.h>
#include <math_constants.h>
#include <cstdint>
#include <cstddef>

#define NDIM 8192
#define CDIM 16
#define K_EDGES 131072
#define MAXDEG 64
#define CAP 512
#define BUF_CAP 33554432u   // 2^25 >= N(N-1)/2 = 33550336 -> can never overflow

static constexpr size_t NN = (size_t)NDIM * (size_t)NDIM;
static constexpr size_t NSLOTS = (size_t)NDIM * (size_t)CAP;

// ---------------- device scratch (static; zero-initialized at load) ----------------
__device__ unsigned long long g_buf[BUF_CAP];   // (bits<<32)|flatIdx candidates (256MB)
__device__ unsigned int  g_bufCnt;
__device__ unsigned char g_labels8[NDIM];
__device__ double        g_sameMass, g_totMass;
__device__ float         g_wsame, g_wdiff;
__device__ int           g_skip;
__device__ int           g_needFallback;
__device__ unsigned int  g_hist1[4096];
__device__ unsigned int  g_hist2[4096];
__device__ unsigned int  g_hist3[256];
__device__ unsigned int  g_bA, g_bAB;
__device__ unsigned int  g_thrBits;
__device__ unsigned int  g_cntGtA, g_cntGtB;
__device__ unsigned int  g_needEq;
__device__ int           g_nbr[NSLOTS];
__device__ float         g_pf[NSLOTS];          // probs[i][j] for slot in row i
__device__ float         g_pr[NSLOTS];          // probs[j][i] for slot in row i
__device__ unsigned char g_act[NSLOTS];         // never needs clearing: emit overwrites 0..degEmit-1
__device__ int           g_deg[NDIM];
__device__ float         g_thr[NDIM];
__device__ unsigned char g_keepall[NDIM];
__device__ unsigned int  g_eqIdx[K_EDGES];
__device__ unsigned int  g_eqCnt;
__device__ int           g_changed[12];

// ---------------- small setup kernels ----------------
__global__ void clearK() {
    int t = threadIdx.x;                 // single block, 1024 threads
    for (int k = t; k < 4096; k += 1024) { g_hist1[k] = 0; g_hist2[k] = 0; }
    for (int k = t; k < 256;  k += 1024) g_hist3[k] = 0;
    for (int k = t; k < NDIM; k += 1024) g_deg[k] = 0;
    if (t < 12) g_changed[t] = (t == 0) ? 1 : 0;
    if (t == 0) {
        g_bufCnt = 0; g_eqCnt = 0; g_needFallback = 0;
        g_sameMass = 0.0; g_totMass = 0.0;
    }
}

__global__ void argmaxK(const float* __restrict__ lp) {
    int i = blockIdx.x * blockDim.x + threadIdx.x;
    if (i >= NDIM) return;
    float best = lp[(size_t)i * CDIM];
    int bi = 0;
#pragma unroll
    for (int c = 1; c < CDIM; c++) {
        float v = lp[(size_t)i * CDIM + c];
        if (v > best) { best = v; bi = c; }
    }
    g_labels8[i] = (unsigned char)bi;
}

// ---------------- mass pass: 256MB read ----------------
__global__ void massK(const float* __restrict__ adj) {
    __shared__ unsigned char slab[NDIM];
    __shared__ double ssh[256], sth[256];
    int i = blockIdx.x, t = threadIdx.x;
    for (int k = t; k < NDIM / 4; k += 256)
        ((unsigned*)slab)[k] = ((const unsigned*)g_labels8)[k];
    __syncthreads();
    unsigned li4 = (unsigned)slab[i] * 0x01010101u;
    const float4* row = (const float4*)(adj + (size_t)i * NDIM);
    float fs = 0.f, ft = 0.f;
    for (int q = t; q < NDIM / 4; q += 256) {
        float4 a = row[q];
        unsigned l4 = ((unsigned*)slab)[q];
        unsigned eq = __vcmpeq4(l4, li4);
        int j0 = q * 4;
        if (i >= j0 && i < j0 + 4) eq &= ~(0xFFu << ((i - j0) * 8));  // diagonal -> diff
        ft += a.x + a.y + a.z + a.w;
        if (eq & 0x000000FFu) fs += a.x;
        if (eq & 0x0000FF00u) fs += a.y;
        if (eq & 0x00FF0000u) fs += a.z;
        if (eq & 0xFF000000u) fs += a.w;
    }
    ssh[t] = (double)fs; sth[t] = (double)ft;
    __syncthreads();
    for (int off = 128; off > 0; off >>= 1) {
        if (t < off) { ssh[t] += ssh[t + off]; sth[t] += sth[t + off]; }
        __syncthreads();
    }
    if (t == 0) { atomicAdd(&g_sameMass, ssh[0]); atomicAdd(&g_totMass, sth[0]); }
}

__global__ void decideK() {
    double sm = g_sameMass, tm = g_totMass;
    double dm = tm - sm;
    float cur = (float)(sm / tm);
    float ws = fminf(fmaxf(0.7f / (cur + 1e-6f), (float)(1.0 / 3.0)), 3.0f);
    float wd = fminf(fmaxf(0.3f / (1.0f - cur + 1e-6f), (float)(1.0 / 3.0)), 3.0f);
    g_wsame = ws; g_wdiff = wd;
    g_skip = (sm <= 1e-6 || dm <= 1e-6 || fabsf(cur - 0.7f) <= 0.05f) ? 1 : 0;
}

// ---------------- P compute + candidate append (no P matrix stored) ----------------
// Primary (FB=false): append elements with bits in [pivot, inf).
// Fallback (FB=true): append elements with bits in [0, pivot) — only if primary
// under-collected (g_needFallback). Disjoint ranges; buffer can hold everything.
template <bool FB>
__global__ void pmatK(const float* __restrict__ adj) {
    if (FB && !g_needFallback) return;
    int bi = blockIdx.y, bj = blockIdx.x;
    if (bj < bi) return;
    __shared__ float sAt[64][65];
    __shared__ unsigned char sli[64], slj[64];
    __shared__ unsigned warpTot[8], warpBase[8];
    __shared__ unsigned blockBase;
    int t = threadIdx.x;
    if (t < 64) { sli[t] = g_labels8[bi * 64 + t]; slj[t] = g_labels8[bj * 64 + t]; }
    for (int e = t; e < 64 * 16; e += 256) {
        int r2 = e >> 4, c4 = (e & 15) * 4;
        float4 v = *(const float4*)(adj + (size_t)(bj * 64 + r2) * NDIM + bi * 64 + c4);
        sAt[r2][c4] = v.x; sAt[r2][c4 + 1] = v.y; sAt[r2][c4 + 2] = v.z; sAt[r2][c4 + 3] = v.w;
    }
    __syncthreads();
    int skip = g_skip;
    float ws = g_wsame, wd = g_wdiff;
    unsigned pivot = skip ? 0x3F000000u : 0x3F800000u;   // 0.5f : 1.0f
    unsigned lo = FB ? 0u : pivot;
    unsigned hi = FB ? pivot : 0xFFFFFFFFu;
    unsigned long long loc[16];
    int cnt = 0;
    for (int e = t; e < 64 * 16; e += 256) {
        int r = e >> 4, c4 = (e & 15) * 4;
        int i = bi * 64 + r;
        int j0 = bj * 64 + c4;
        float4 a = *(const float4*)(adj + (size_t)i * NDIM + j0);
        float av[4] = {a.x, a.y, a.z, a.w};
#pragma unroll
        for (int k = 0; k < 4; k++) {
            int j = j0 + k;
            if (j <= i) continue;
            float p;
            if (skip) p = av[k];
            else {
                float w = (sli[r] == slj[c4 + k]) ? ws : wd;
                p = 0.5f * __fadd_rn(__fmul_rn(av[k], w), __fmul_rn(sAt[c4 + k][r], w));
            }
            unsigned bits = __float_as_uint(p);
            if (bits >= lo && bits < hi)
                loc[cnt++] = ((unsigned long long)bits << 32) | (unsigned)(i * NDIM + j);
        }
    }
    // block-aggregated append: warp scans + one global atomic per block
    unsigned pre = (unsigned)cnt;
    for (int d = 1; d < 32; d <<= 1) {
        unsigned v = __shfl_up_sync(0xFFFFFFFFu, pre, d);
        if ((t & 31) >= d) pre += v;
    }
    if ((t & 31) == 31) warpTot[t >> 5] = pre;
    __syncthreads();
    if (t == 0) {
        unsigned s = 0;
        for (int w = 0; w < 8; w++) { unsigned v = warpTot[w]; warpBase[w] = s; s += v; }
        blockBase = s ? atomicAdd(&g_bufCnt, s) : 0u;
    }
    __syncthreads();
    unsigned base = blockBase + warpBase[t >> 5] + (pre - (unsigned)cnt);
    for (int k = 0; k < cnt; k++) {
        unsigned pos = base + (unsigned)k;
        if (pos < BUF_CAP) g_buf[pos] = loc[k];
    }
}

__global__ void flagK() { g_needFallback = (g_bufCnt < (unsigned)K_EDGES) ? 1 : 0; }

// ---------------- radix selection over candidate buffer ----------------
__global__ void histAK() {
    __shared__ unsigned sh[4096];
    for (int k = threadIdx.x; k < 4096; k += 256) sh[k] = 0;
    __syncthreads();
    unsigned n = min(g_bufCnt, BUF_CAP);
    for (unsigned idx = blockIdx.x * 256u + threadIdx.x; idx < n; idx += gridDim.x * 256u)
        atomicAdd(&sh[(unsigned)(g_buf[idx] >> 32) >> 20], 1u);
    __syncthreads();
    for (int k = threadIdx.x; k < 4096; k += 256)
        if (sh[k]) atomicAdd(&g_hist1[k], sh[k]);
}

__global__ void scanAK() {
    unsigned cum = 0;
    for (int k = 4095; k >= 0; k--) {
        unsigned h = g_hist1[k];
        if (cum + h >= (unsigned)K_EDGES) { g_bA = (unsigned)k; g_cntGtA = cum; return; }
        cum += h;
    }
    g_bA = 0; g_cntGtA = cum;
}

__global__ void histBK() {
    __shared__ unsigned sh[4096];
    for (int k = threadIdx.x; k < 4096; k += 256) sh[k] = 0;
    __syncthreads();
    unsigned n = min(g_bufCnt, BUF_CAP);
    unsigned bA = g_bA;
    for (unsigned idx = blockIdx.x * 256u + threadIdx.x; idx < n; idx += gridDim.x * 256u) {
        unsigned bits = (unsigned)(g_buf[idx] >> 32);
        if ((bits >> 20) == bA) atomicAdd(&sh[(bits >> 8) & 0xFFFu], 1u);
    }
    __syncthreads();
    for (int k = threadIdx.x; k < 4096; k += 256)
        if (sh[k]) atomicAdd(&g_hist2[k], sh[k]);
}

__global__ void scanBK() {
    unsigned cum = g_cntGtA;
    for (int k = 4095; k >= 0; k--) {
        unsigned h = g_hist2[k];
        if (cum + h >= (unsigned)K_EDGES) { g_bAB = (g_bA << 12) | (unsigned)k; g_cntGtB = cum; return; }
        cum += h;
    }
    g_bAB = (g_bA << 12); g_cntGtB = cum;
}

__global__ void histCK() {
    __shared__ unsigned sh[256];
    if (threadIdx.x < 256) sh[threadIdx.x] = 0;
    __syncthreads();
    unsigned n = min(g_bufCnt, BUF_CAP);
    unsigned bAB = g_bAB;
    for (unsigned idx = blockIdx.x * 256u + threadIdx.x; idx < n; idx += gridDim.x * 256u) {
        unsigned bits = (unsigned)(g_buf[idx] >> 32);
        if ((bits >> 8) == bAB) atomicAdd(&sh[bits & 0xFFu], 1u);
    }
    __syncthreads();
    if (threadIdx.x < 256 && sh[threadIdx.x]) atomicAdd(&g_hist3[threadIdx.x], sh[threadIdx.x]);
}

__global__ void scanCK() {
    unsigned cum = g_cntGtB;
    for (int k = 255; k >= 0; k--) {
        unsigned h = g_hist3[k];
        if (cum + h >= (unsigned)K_EDGES) {
            g_thrBits = (g_bAB << 8) | (unsigned)k;
            g_needEq = (unsigned)K_EDGES - cum;
            return;
        }
        cum += h;
    }
    g_thrBits = (g_bAB << 8); g_needEq = 0;
}

// ---------------- edge emission ----------------
__device__ __forceinline__ void emitEdge(int i, int j, float p,
                                         const float* __restrict__ adj, int skip) {
    float pf_i, pr_i, pf_j, pr_j;
    if (skip) {
        float aij = adj[(size_t)i * NDIM + j];
        float aji = adj[(size_t)j * NDIM + i];
        pf_i = aij; pr_i = aji; pf_j = aji; pr_j = aij;
    } else {
        pf_i = pr_i = pf_j = pr_j = p;
    }
    int di = atomicAdd(&g_deg[i], 1);
    if (di < CAP) {
        size_t s = (size_t)i * CAP + di;
        g_nbr[s] = j; g_pf[s] = pf_i; g_pr[s] = pr_i; g_act[s] = 1;
    }
    int dj = atomicAdd(&g_deg[j], 1);
    if (dj < CAP) {
        size_t s = (size_t)j * CAP + dj;
        g_nbr[s] = i; g_pf[s] = pf_j; g_pr[s] = pr_j; g_act[s] = 1;
    }
}

__global__ void selectBufK(const float* __restrict__ adj) {
    unsigned n = min(g_bufCnt, BUF_CAP);
    unsigned thr = g_thrBits;
    int skip = g_skip;
    for (unsigned idx = blockIdx.x * 256u + threadIdx.x; idx < n; idx += gridDim.x * 256u) {
        unsigned long long e = g_buf[idx];
        unsigned bits = (unsigned)(e >> 32);
        if (bits > thr) {
            unsigned fi = (unsigned)e;
            emitEdge((int)(fi >> 13), (int)(fi & 8191u), __uint_as_float(bits), adj, skip);
        } else if (bits == thr) {
            unsigned pos = atomicAdd(&g_eqCnt, 1u);
            if (pos < (unsigned)K_EDGES) g_eqIdx[pos] = (unsigned)e;
        }
    }
}

// lax.top_k tie-break: among ==thr entries, lowest flat index wins.
__global__ void resolveK(const float* __restrict__ adj) {
    unsigned M = min(g_eqCnt, (unsigned)K_EDGES);
    unsigned need = g_needEq;
    int skip = g_skip;
    if (need == 0) return;
    unsigned stride = gridDim.x * blockDim.x;
    unsigned thr = g_thrBits;
    for (unsigned t = blockIdx.x * blockDim.x + threadIdx.x; t < M; t += stride) {
        unsigned idx = g_eqIdx[t];
        unsigned rank = 0;
        for (unsigned s = 0; s < M; s++) rank += (g_eqIdx[s] < idx) ? 1u : 0u;
        if (rank < need)
            emitEdge((int)(idx >> 13), (int)(idx & 8191u), __uint_as_float(thr), adj, skip);
    }
}

// ---------------- degree-cap loop (warp per row, early-exit on fixed point) ----------------
__global__ void threshK(int iter) {
    if (!g_changed[iter]) return;
    int lane = threadIdx.x & 31;
    int i = blockIdx.x * 8 + (threadIdx.x >> 5);
    size_t base = (size_t)i * CAP;
    float v[16];
    unsigned am = 0;
    int dcnt = 0;
#pragma unroll
    for (int k = 0; k < 16; k++) {
        int s = lane + k * 32;
        if (g_act[base + s]) { v[k] = g_pf[base + s]; am |= 1u << k; dcnt++; }
    }
    int deg = (int)__reduce_add_sync(0xFFFFFFFFu, (unsigned)dcnt);
    if (deg <= MAXDEG) { if (lane == 0) g_keepall[i] = 1; return; }
    if (lane == 0) g_keepall[i] = 0;
    unsigned T = 0;
    for (int b = 31; b >= 0; b--) {
        unsigned cand = T | (1u << b);
        unsigned c = 0;
#pragma unroll
        for (int k = 0; k < 16; k++)
            if (((am >> k) & 1u) && __float_as_uint(v[k]) >= cand) c++;
        c = __reduce_add_sync(0xFFFFFFFFu, c);
        if (c >= (unsigned)MAXDEG) T = cand;
    }
    if (lane == 0) g_thr[i] = __uint_as_float(T);
}

__global__ void filterK(int iter) {
    if (!g_changed[iter]) return;
    size_t idx = blockIdx.x * (size_t)blockDim.x + threadIdx.x;
    if (idx >= NSLOTS) return;
    if (!g_act[idx]) return;
    int i = (int)(idx >> 9);
    int j = g_nbr[idx];
    bool ki = g_keepall[i] ? true : (g_pf[idx] >= g_thr[i]);
    bool kj = g_keepall[j] ? true : (g_pr[idx] >= g_thr[j]);
    if (!(ki && kj)) { g_act[idx] = 0; g_changed[iter + 1] = 1; }
}

// ---------------- fused zero + scatter output (one clean 256MB write) ----------------
__global__ void outK(float* __restrict__ out) {
    __shared__ unsigned sBits[256];   // 8192-bit row mask
    int i = blockIdx.x, t = threadIdx.x;
    sBits[t] = 0;
    __syncthreads();
    size_t base = (size_t)i * CAP;
    for (int s = t; s < CAP; s += 256)
        if (g_act[base + s]) {
            int j = g_nbr[base + s];
            atomicOr(&sBits[j >> 5], 1u << (j & 31));
        }
    __syncthreads();
    float4* orow = (float4*)(out + (size_t)i * NDIM);
    for (int q = t; q < NDIM / 4; q += 256) {
        unsigned w = sBits[q >> 3];
        unsigned sh = (q & 7) * 4;
        float4 v;
        v.x = (w >> sh & 1u) ? 1.f : 0.f;
        v.y = (w >> (sh + 1) & 1u) ? 1.f : 0.f;
        v.z = (w >> (sh + 2) & 1u) ? 1.f : 0.f;
        v.w = (w >> (sh + 3) & 1u) ? 1.f : 0.f;
        orow[q] = v;
    }
}

// ---------------- launch ----------------
extern "C" void kernel_launch(void* const* d_in, const int* in_sizes, int n_in,
                              void* d_out, int out_size) {
    const float* adj = (const float*)d_in[0];
    const float* lp  = (const float*)d_in[1];
    float* out = (float*)d_out;

    clearK<<<1, 1024>>>();
    argmaxK<<<NDIM / 256, 256>>>(lp);
    massK<<<NDIM, 256>>>(adj);
    decideK<<<1, 1>>>();
    {
        dim3 grid(128, 128);
        pmatK<false><<<grid, 256>>>(adj);
        flagK<<<1, 1>>>();
        pmatK<true><<<grid, 256>>>(adj);
    }
    histAK<<<512, 256>>>();
    scanAK<<<1, 1>>>();
    histBK<<<512, 256>>>();
    scanBK<<<1, 1>>>();
    histCK<<<512, 256>>>();
    scanCK<<<1, 1>>>();
    selectBufK<<<512, 256>>>(adj);
    resolveK<<<64, 256>>>(adj);

    for (int it = 0; it < 10; it++) {
        threshK<<<NDIM / 8, 256>>>(it);
        filterK<<<(int)(NSLOTS / 256), 256>>>(it);
    }

    outK<<<NDIM, 256>>>(out);
}

// round 3
// speedup vs baseline: 4.1589x; 1.7624x over previous
#include <cuda_runtime.h>
#include <cstdint>
#include <cstddef>

#define NDIM 8192
#define CDIM 16
#define KSEL 131072u
#define MAXDEG 64
#define CAP 512
#define BUF_CAP 33554432u   // 2^25 >= N(N-1)/2 -> full fallback always fits
#define LOOP_BLOCKS 128

static constexpr size_t NN = (size_t)NDIM * (size_t)NDIM;
static constexpr size_t NSLOTS = (size_t)NDIM * (size_t)CAP;

// ---------------- device scratch ----------------
__device__ unsigned long long g_buf[BUF_CAP];
__device__ unsigned int  g_bufCnt;
__device__ unsigned char g_labels8[NDIM];
__device__ double        g_sameMass, g_totMass;
__device__ float         g_wsame, g_wdiff;
__device__ int           g_skip;
__device__ int           g_needFallback;
__device__ unsigned int  g_hist1[4096];
__device__ unsigned int  g_hist2[4096];
__device__ unsigned int  g_hist3[256];
__device__ unsigned int  g_bA, g_bAB;
__device__ unsigned int  g_thrBits;
__device__ unsigned int  g_cntGtA, g_cntGtB;
__device__ unsigned int  g_needEq;
__device__ int           g_nbr[NSLOTS];
__device__ float         g_pf[NSLOTS];
__device__ float         g_pr[NSLOTS];
__device__ unsigned char g_act[NSLOTS];
__device__ int           g_deg[NDIM];
__device__ unsigned int  g_thrU[NDIM];
__device__ unsigned char g_keepall[NDIM];
__device__ unsigned int  g_eqIdx[KSEL];
__device__ unsigned int  g_eqCnt;
__device__ unsigned int  g_changedArr[12];
__device__ unsigned int  g_tk[8];          // per-kernel "last block" tickets
__device__ unsigned int  g_barCount, g_barGen;

// ---------------- helpers ----------------
__device__ __forceinline__ void gridBar() {
    __syncthreads();
    if (threadIdx.x == 0) {
        unsigned gen = atomicAdd(&g_barGen, 0u);
        __threadfence();
        if (atomicAdd(&g_barCount, 1u) == LOOP_BLOCKS - 1) {
            g_barCount = 0u;
            __threadfence();
            atomicAdd(&g_barGen, 1u);
        } else {
            unsigned spins = 0;
            while (atomicAdd(&g_barGen, 0u) == gen) {
                if (++spins > (1u << 28)) break;  // safety valve
                __nanosleep(64);
            }
        }
    }
    __syncthreads();
}

// Block-parallel "find top-K boundary bin" over a 4096-bin histogram.
// Requires 256 participating threads. cumGe(b) = base + sum_{b'>=b} h[b'].
// Picks largest b with cumGe(b) >= K: writes bin and cntGt = cumGe(b+1).
__device__ void scanSelect4096(const unsigned* hist, unsigned baseCum,
                               unsigned* outBin, unsigned* outCntGt) {
    __shared__ unsigned part[256];
    int t = threadIdx.x;
    unsigned local[16];
    unsigned s = 0;
#pragma unroll
    for (int k = 0; k < 16; k++) { local[k] = hist[t * 16 + k]; s += local[k]; }
    part[t] = s;
    __syncthreads();
    for (int off = 1; off < 256; off <<= 1) {
        unsigned v = (t + off < 256) ? part[t + off] : 0u;
        __syncthreads();
        part[t] += v;
        __syncthreads();
    }
    unsigned suf = (t < 255) ? part[t + 1] : 0u;   // sum over bins above this thread's range
    unsigned cum = baseCum + suf;
#pragma unroll
    for (int k = 15; k >= 0; k--) {
        unsigned h = local[k];
        unsigned cg = cum + h;
        if (cg >= KSEL && cum < KSEL) { *outBin = (unsigned)(t * 16 + k); *outCntGt = cum; }
        cum = cg;
    }
}

__device__ void scanSelect256(const unsigned* hist, unsigned baseCum, unsigned prefix12) {
    __shared__ unsigned part2[256];
    int t = threadIdx.x;
    unsigned h = hist[t];
    part2[t] = h;
    __syncthreads();
    for (int off = 1; off < 256; off <<= 1) {
        unsigned v = (t + off < 256) ? part2[t + off] : 0u;
        __syncthreads();
        part2[t] += v;
        __syncthreads();
    }
    unsigned cum = baseCum + ((t < 255) ? part2[t + 1] : 0u);
    unsigned cg = cum + h;
    if (cg >= KSEL && cum < KSEL) {
        g_thrBits = (prefix12 << 8) | (unsigned)t;
        g_needEq = KSEL - cum;
    }
}

// ---------------- setup ----------------
__global__ void clearK() {
    int t = threadIdx.x;  // 1 block, 1024 threads
    for (int k = t; k < 4096; k += 1024) { g_hist1[k] = 0; g_hist2[k] = 0; }
    for (int k = t; k < 256;  k += 1024) g_hist3[k] = 0;
    for (int k = t; k < NDIM; k += 1024) g_deg[k] = 0;
    if (t < 12) g_changedArr[t] = 0;
    if (t < 8)  g_tk[t] = 0;
    if (t == 0) {
        g_bufCnt = 0; g_eqCnt = 0; g_needFallback = 0;
        g_sameMass = 0.0; g_totMass = 0.0;
        g_needEq = 0; g_thrBits = 0xFFFFFFFFu;
    }
}

__global__ void argmaxK(const float* __restrict__ lp) {
    int i = blockIdx.x * blockDim.x + threadIdx.x;
    if (i >= NDIM) return;
    float best = lp[(size_t)i * CDIM];
    int bi = 0;
#pragma unroll
    for (int c = 1; c < CDIM; c++) {
        float v = lp[(size_t)i * CDIM + c];
        if (v > best) { best = v; bi = c; }
    }
    g_labels8[i] = (unsigned char)bi;
}

// ---------------- mass pass (decide folded into last block) ----------------
__global__ void massK(const float* __restrict__ adj) {
    __shared__ unsigned char slab[NDIM];
    __shared__ double ssh[256], sth[256];
    int i = blockIdx.x, t = threadIdx.x;
    for (int k = t; k < NDIM / 4; k += 256)
        ((unsigned*)slab)[k] = ((const unsigned*)g_labels8)[k];
    __syncthreads();
    unsigned li4 = (unsigned)slab[i] * 0x01010101u;
    const float4* row = (const float4*)(adj + (size_t)i * NDIM);
    float fs = 0.f, ft = 0.f;
    for (int q = t; q < NDIM / 4; q += 256) {
        float4 a = __ldcs(&row[q]);
        unsigned l4 = ((unsigned*)slab)[q];
        unsigned eq = __vcmpeq4(l4, li4);
        int j0 = q * 4;
        if (i >= j0 && i < j0 + 4) eq &= ~(0xFFu << ((i - j0) * 8));
        ft += a.x + a.y + a.z + a.w;
        if (eq & 0x000000FFu) fs += a.x;
        if (eq & 0x0000FF00u) fs += a.y;
        if (eq & 0x00FF0000u) fs += a.z;
        if (eq & 0xFF000000u) fs += a.w;
    }
    ssh[t] = (double)fs; sth[t] = (double)ft;
    __syncthreads();
    for (int off = 128; off > 0; off >>= 1) {
        if (t < off) { ssh[t] += ssh[t + off]; sth[t] += sth[t + off]; }
        __syncthreads();
    }
    if (t == 0) {
        atomicAdd(&g_sameMass, ssh[0]);
        atomicAdd(&g_totMass, sth[0]);
        __threadfence();
        if (atomicAdd(&g_tk[0], 1u) == gridDim.x - 1) {   // last block: decide
            double sm = g_sameMass, tm = g_totMass;
            double dm = tm - sm;
            float cur = (float)(sm / tm);
            g_wsame = fminf(fmaxf(0.7f / (cur + 1e-6f), (float)(1.0 / 3.0)), 3.0f);
            g_wdiff = fminf(fmaxf(0.3f / (1.0f - cur + 1e-6f), (float)(1.0 / 3.0)), 3.0f);
            g_skip = (sm <= 1e-6 || dm <= 1e-6 || fabsf(cur - 0.7f) <= 0.05f) ? 1 : 0;
        }
    }
}

// ---------------- P compute + candidate append + level-1 hist ----------------
// FB=false: append bits in [pivot, inf) + last block sets fallback flag.
// FB=true:  append bits in [0, pivot) only if needed + last block runs scanA.
template <bool FB>
__global__ void pmatK(const float* __restrict__ adj) {
    __shared__ float sAt[64][65];
    __shared__ unsigned char sli[64], slj[64];
    __shared__ unsigned shH[4096];
    __shared__ unsigned warpTot[8], warpBase[8];
    __shared__ unsigned blockBase;
    __shared__ int sLast;
    int t = threadIdx.x;
    int bi = blockIdx.y, bj = blockIdx.x;
    bool doWork = (bj >= bi) && (!FB || g_needFallback);

    if (doWork) {
        for (int k = t; k < 4096; k += 256) shH[k] = 0;
        if (t < 64) { sli[t] = g_labels8[bi * 64 + t]; slj[t] = g_labels8[bj * 64 + t]; }
        for (int e = t; e < 64 * 16; e += 256) {
            int r2 = e >> 4, c4 = (e & 15) * 4;
            float4 v = __ldcs((const float4*)(adj + (size_t)(bj * 64 + r2) * NDIM + bi * 64 + c4));
            sAt[r2][c4] = v.x; sAt[r2][c4 + 1] = v.y; sAt[r2][c4 + 2] = v.z; sAt[r2][c4 + 3] = v.w;
        }
        __syncthreads();
        int skip = g_skip;
        float ws = g_wsame, wd = g_wdiff;
        unsigned pivot = skip ? 0x3F000000u : 0x3F800000u;
        unsigned lo = FB ? 0u : pivot;
        unsigned hi = FB ? pivot : 0xFFFFFFFFu;
        unsigned long long loc[16];
        int cnt = 0;
        for (int e = t; e < 64 * 16; e += 256) {
            int r = e >> 4, c4 = (e & 15) * 4;
            int i = bi * 64 + r;
            int j0 = bj * 64 + c4;
            float4 a = __ldcs((const float4*)(adj + (size_t)i * NDIM + j0));
            float av[4] = {a.x, a.y, a.z, a.w};
#pragma unroll
            for (int k = 0; k < 4; k++) {
                int j = j0 + k;
                if (j <= i) continue;
                float p;
                if (skip) p = av[k];
                else {
                    float w = (sli[r] == slj[c4 + k]) ? ws : wd;
                    p = 0.5f * __fadd_rn(__fmul_rn(av[k], w), __fmul_rn(sAt[c4 + k][r], w));
                }
                unsigned bits = __float_as_uint(p);
                if (bits >= lo && bits < hi) {
                    loc[cnt++] = ((unsigned long long)bits << 32) | (unsigned)(i * NDIM + j);
                    atomicAdd(&shH[bits >> 20], 1u);
                }
            }
        }
        // block-aggregated buffer append
        unsigned pre = (unsigned)cnt;
        for (int d = 1; d < 32; d <<= 1) {
            unsigned v = __shfl_up_sync(0xFFFFFFFFu, pre, d);
            if ((t & 31) >= d) pre += v;
        }
        if ((t & 31) == 31) warpTot[t >> 5] = pre;
        __syncthreads();
        if (t == 0) {
            unsigned s = 0;
            for (int w = 0; w < 8; w++) { unsigned v = warpTot[w]; warpBase[w] = s; s += v; }
            blockBase = s ? atomicAdd(&g_bufCnt, s) : 0u;
        }
        __syncthreads();
        unsigned base = blockBase + warpBase[t >> 5] + (pre - (unsigned)cnt);
        for (int k = 0; k < cnt; k++) {
            unsigned pos = base + (unsigned)k;
            if (pos < BUF_CAP) g_buf[pos] = loc[k];
        }
        // merge hist (few nonzero bins)
        for (int k = t; k < 4096; k += 256)
            if (shH[k]) atomicAdd(&g_hist1[k], shH[k]);
    }
    __syncthreads();
    if (t == 0) {
        __threadfence();
        unsigned tk = atomicAdd(&g_tk[FB ? 2 : 1], 1u);
        sLast = (tk == gridDim.x * gridDim.y - 1) ? 1 : 0;
    }
    __syncthreads();
    if (sLast) {
        if (!FB) {
            if (t == 0) g_needFallback = (g_bufCnt < KSEL) ? 1 : 0;
        } else {
            scanSelect4096(g_hist1, 0u, &g_bA, &g_cntGtA);   // one thread writes
        }
    }
}

// ---------------- level-2 / level-3 hist (scan folded into last block) ----------------
__global__ void histBK() {
    __shared__ unsigned sh[4096];
    __shared__ int sLast;
    int t = threadIdx.x;
    for (int k = t; k < 4096; k += 256) sh[k] = 0;
    __syncthreads();
    unsigned n = min(g_bufCnt, BUF_CAP);
    unsigned bA = g_bA;
    for (unsigned idx = blockIdx.x * 256u + t; idx < n; idx += gridDim.x * 256u) {
        unsigned bits = (unsigned)(__ldcs(&g_buf[idx]) >> 32);
        if ((bits >> 20) == bA) atomicAdd(&sh[(bits >> 8) & 0xFFFu], 1u);
    }
    __syncthreads();
    for (int k = t; k < 4096; k += 256)
        if (sh[k]) atomicAdd(&g_hist2[k], sh[k]);
    __syncthreads();
    if (t == 0) {
        __threadfence();
        sLast = (atomicAdd(&g_tk[3], 1u) == gridDim.x - 1) ? 1 : 0;
    }
    __syncthreads();
    if (sLast) {
        __shared__ unsigned binOut;
        scanSelect4096(g_hist2, g_cntGtA, &binOut, &g_cntGtB);
        __syncthreads();
        if (t == 0) g_bAB = (g_bA << 12) | binOut;
    }
}

__global__ void histCK() {
    __shared__ unsigned sh[256];
    __shared__ int sLast;
    int t = threadIdx.x;
    sh[t] = 0;
    __syncthreads();
    unsigned n = min(g_bufCnt, BUF_CAP);
    unsigned bAB = g_bAB;
    for (unsigned idx = blockIdx.x * 256u + t; idx < n; idx += gridDim.x * 256u) {
        unsigned bits = (unsigned)(__ldcs(&g_buf[idx]) >> 32);
        if ((bits >> 8) == bAB) atomicAdd(&sh[bits & 0xFFu], 1u);
    }
    __syncthreads();
    if (sh[t]) atomicAdd(&g_hist3[t], sh[t]);
    __syncthreads();
    if (t == 0) {
        __threadfence();
        sLast = (atomicAdd(&g_tk[4], 1u) == gridDim.x - 1) ? 1 : 0;
    }
    __syncthreads();
    if (sLast) scanSelect256(g_hist3, g_cntGtB, g_bAB);
}

// ---------------- edge emission ----------------
__device__ __forceinline__ void emitEdge(int i, int j, float p,
                                         const float* __restrict__ adj, int skip) {
    float pf_i, pr_i, pf_j, pr_j;
    if (skip) {
        float aij = adj[(size_t)i * NDIM + j];
        float aji = adj[(size_t)j * NDIM + i];
        pf_i = aij; pr_i = aji; pf_j = aji; pr_j = aij;
    } else {
        pf_i = pr_i = pf_j = pr_j = p;
    }
    int di = atomicAdd(&g_deg[i], 1);
    if (di < CAP) {
        size_t s = (size_t)i * CAP + di;
        g_nbr[s] = j; g_pf[s] = pf_i; g_pr[s] = pr_i; g_act[s] = 1;
    }
    int dj = atomicAdd(&g_deg[j], 1);
    if (dj < CAP) {
        size_t s = (size_t)j * CAP + dj;
        g_nbr[s] = i; g_pf[s] = pf_j; g_pr[s] = pr_j; g_act[s] = 1;
    }
}

__global__ void selectBufK(const float* __restrict__ adj) {
    unsigned n = min(g_bufCnt, BUF_CAP);
    unsigned thr = g_thrBits;
    int skip = g_skip;
    for (unsigned idx = blockIdx.x * 256u + threadIdx.x; idx < n; idx += gridDim.x * 256u) {
        unsigned long long e = __ldcs(&g_buf[idx]);
        unsigned bits = (unsigned)(e >> 32);
        if (bits > thr) {
            unsigned fi = (unsigned)e;
            emitEdge((int)(fi >> 13), (int)(fi & 8191u), __uint_as_float(bits), adj, skip);
        } else if (bits == thr) {
            unsigned pos = atomicAdd(&g_eqCnt, 1u);
            if (pos < KSEL) g_eqIdx[pos] = (unsigned)e;
        }
    }
}

// ---------------- persistent kernel: tie-resolve + degree-cap loop ----------------
__global__ void __launch_bounds__(1024, 1) loopK(const float* __restrict__ adj) {
    // phase 0: tie resolution (lowest flat index wins, matching lax.top_k)
    {
        unsigned M = min(g_eqCnt, KSEL);
        unsigned need = g_needEq;
        int skip = g_skip;
        if (need > 0) {
            for (unsigned u = blockIdx.x * 1024u + threadIdx.x; u < M; u += LOOP_BLOCKS * 1024u) {
                unsigned idx = g_eqIdx[u];
                unsigned rank = 0;
                for (unsigned s = 0; s < M; s++) rank += (g_eqIdx[s] < idx) ? 1u : 0u;
                if (rank < need)
                    emitEdge((int)(idx >> 13), (int)(idx & 8191u),
                             __uint_as_float(g_thrBits), adj, skip);
            }
        }
    }
    gridBar();

    int lane = threadIdx.x & 31;
    int warpG = blockIdx.x * 32 + (threadIdx.x >> 5);
    const int nW = LOOP_BLOCKS * 32;
    __shared__ unsigned sCont;

    for (int iter = 0; iter < 10; iter++) {
        // --- thresh phase: per-row 64th-largest active value ---
        for (int i = warpG; i < NDIM; i += nW) {
            size_t base = (size_t)i * CAP;
            int degE = min(g_deg[i], CAP);
            float v[16]; unsigned am = 0, dc = 0;
#pragma unroll
            for (int k = 0; k < 16; k++) {
                int s = lane + k * 32;
                bool a = (s < degE) && (__ldcg(&g_act[base + s]) != 0);
                if (a) { v[k] = g_pf[base + s]; am |= 1u << k; dc++; }
            }
            unsigned deg = __reduce_add_sync(0xFFFFFFFFu, dc);
            if (deg <= (unsigned)MAXDEG) {
                if (lane == 0) __stcg(&g_keepall[i], (unsigned char)1);
                continue;
            }
            if (lane == 0) __stcg(&g_keepall[i], (unsigned char)0);
            unsigned T = 0;
            for (int b = 31; b >= 0; b--) {
                unsigned cand = T | (1u << b);
                unsigned c = 0;
#pragma unroll
                for (int k = 0; k < 16; k++)
                    if (((am >> k) & 1u) && __float_as_uint(v[k]) >= cand) c++;
                c = __reduce_add_sync(0xFFFFFFFFu, c);
                if (c >= (unsigned)MAXDEG) T = cand;
            }
            if (lane == 0) __stcg(&g_thrU[i], T);
        }
        gridBar();
        // --- filter phase ---
        bool removed = false;
        for (int i = warpG; i < NDIM; i += nW) {
            size_t base = (size_t)i * CAP;
            int degE = min(g_deg[i], CAP);
            unsigned kaI = __ldcg(&g_keepall[i]);
            unsigned thrI = __ldcg(&g_thrU[i]);
            for (int s = lane; s < degE; s += 32) {
                if (!__ldcg(&g_act[base + s])) continue;
                int j = g_nbr[base + s];
                bool ki = kaI || (__float_as_uint(g_pf[base + s]) >= thrI);
                bool kj = __ldcg(&g_keepall[j]) ||
                          (__float_as_uint(g_pr[base + s]) >= __ldcg(&g_thrU[j]));
                if (!(ki && kj)) { __stcg(&g_act[base + s], (unsigned char)0); removed = true; }
            }
        }
        if (__any_sync(0xFFFFFFFFu, removed) && lane == 0)
            atomicOr(&g_changedArr[iter + 1], 1u);
        gridBar();
        if (threadIdx.x == 0) sCont = atomicAdd(&g_changedArr[iter + 1], 0u);
        __syncthreads();
        if (!sCont) break;   // fixed point: remaining iterations are provably no-ops
    }
}

// ---------------- fused zero + scatter output ----------------
__global__ void outK(float* __restrict__ out) {
    __shared__ unsigned sBits[256];
    int i = blockIdx.x, t = threadIdx.x;
    sBits[t] = 0;
    __syncthreads();
    size_t base = (size_t)i * CAP;
    int degE = min(g_deg[i], CAP);
    for (int s = t; s < degE; s += 256)
        if (g_act[base + s]) {
            int j = g_nbr[base + s];
            atomicOr(&sBits[j >> 5], 1u << (j & 31));
        }
    __syncthreads();
    float4* orow = (float4*)(out + (size_t)i * NDIM);
    for (int q = t; q < NDIM / 4; q += 256) {
        unsigned w = sBits[q >> 3];
        unsigned sh = (q & 7) * 4;
        float4 v;
        v.x = (w >> sh & 1u) ? 1.f : 0.f;
        v.y = (w >> (sh + 1) & 1u) ? 1.f : 0.f;
        v.z = (w >> (sh + 2) & 1u) ? 1.f : 0.f;
        v.w = (w >> (sh + 3) & 1u) ? 1.f : 0.f;
        __stcs(&orow[q], v);
    }
}

// ---------------- launch ----------------
extern "C" void kernel_launch(void* const* d_in, const int* in_sizes, int n_in,
                              void* d_out, int out_size) {
    const float* adj = (const float*)d_in[0];
    const float* lp  = (const float*)d_in[1];
    float* out = (float*)d_out;

    clearK<<<1, 1024>>>();
    argmaxK<<<NDIM / 256, 256>>>(lp);
    massK<<<NDIM, 256>>>(adj);                 // + decide (last block)
    {
        dim3 grid(128, 128);
        pmatK<false><<<grid, 256>>>(adj);      // + fallback flag (last block)
        pmatK<true><<<grid, 256>>>(adj);       // + scanA (last block)
    }
    histBK<<<512, 256>>>();                    // + scanB (last block)
    histCK<<<512, 256>>>();                    // + scanC (last block)
    selectBufK<<<512, 256>>>(adj);
    loopK<<<LOOP_BLOCKS, 1024>>>(adj);         // tie-resolve + pruning loop (early exit)
    outK<<<NDIM, 256>>>(out);
}